// round 9
// baseline (speedup 1.0000x reference)
#include <cuda_runtime.h>
#include <cuda_bf16.h>

// Problem constants (fixed by setup_inputs): length=8192, n=4096.
#define ENC_LEN    8192
#define BLOCK      512
#define ROWS_PER_CTA 7   // 585 CTAs * 7 rows + 1 = 4096; grid = 586

// inv_freq(base) = 1000^(-base/8192) = exp2(-(base/8192) * log2(1000))
// Compensated fp32 product keeps the exp2 argument accurate to ~1 ulp.
__device__ __forceinline__ float inv_freq(int base) {
    const double Ld = 9.965784284662087;          // log2(1000)
    const float  Lh = (float)Ld;
    const float  Ll = (float)(Ld - (double)Lh);   // low-order correction
    float e   = (float)base * (1.0f / 8192.0f);   // exact (base < 2^13)
    float p   = e * Lh;
    float err = fmaf(e, Lh, -p);                  // exact residual of e*Lh
    float t   = p + fmaf(e, Ll, err);             // ≈ e * log2(1000)
    return exp2f(-t);
}

__device__ __forceinline__ unsigned long long pack2(float x, float y) {
    unsigned long long r;
    asm("mov.b64 %0, {%1, %2};" : "=l"(r) : "f"(x), "f"(y));
    return r;
}

// Plain 32-byte store, default L2 policy (measured best across all hint
// variants: .cs / evict_last never beat default on the steady-state period).
__device__ __forceinline__ void st32B(void* p, const unsigned long long* q) {
    asm volatile("st.global.v4.b64 [%0], {%1, %2, %3, %4};"
                 :: "l"(p), "l"(q[0]), "l"(q[1]), "l"(q[2]), "l"(q[3])
                 : "memory");
}

// ---------------------------------------------------------------------------
// Fused kernel. Each thread owns two contiguous 32B chunks of the row:
//   chunk A: elements [8t, 8t+8)
//   chunk B: elements [8t+4096, 8t+4104)
// computed once into registers (8 sincosf + 8 exp2f). Each CTA then writes a
// CONTIGUOUS block of up to 7 rows, fully unrolled (14 independent 256-bit
// stores issued back-to-back). Balanced makespan: max 7 rows/CTA (the strided
// scheme had a 8-vs-6 row imbalance). Runtime: HBM/LTS write-bound.
// ---------------------------------------------------------------------------
__global__ void __launch_bounds__(BLOCK)
sinusoidal_fused_kernel(const float* __restrict__ position,
                        float* __restrict__ out, int n) {
    const int tid = threadIdx.x;
    const float pos = position[0];

    unsigned long long qa[4], qb[4];
#pragma unroll
    for (int k = 0; k < 4; ++k) {
        int baseA = 8 * tid + 2 * k;
        float aA = pos * inv_freq(baseA);
        float sA, cA;
        sincosf(aA, &sA, &cA);
        qa[k] = pack2(sA, cA);

        int baseB = baseA + 4096;
        float aB = pos * inv_freq(baseB);
        float sB, cB;
        sincosf(aB, &sB, &cB);
        qb[k] = pack2(sB, cB);
    }

    const int offA = 8 * tid;
    const int offB = 8 * tid + 4096;

    const int row0 = blockIdx.x * ROWS_PER_CTA;
    float* __restrict__ base = out + (size_t)row0 * ENC_LEN;

    if (row0 + ROWS_PER_CTA <= n) {
        // Full block: 14 independent stores, no branches.
#pragma unroll
        for (int r = 0; r < ROWS_PER_CTA; ++r) {
            float* __restrict__ d = base + (size_t)r * ENC_LEN;
            st32B(d + offA, qa);
            st32B(d + offB, qb);
        }
    } else {
        for (int r = 0; row0 + r < n; ++r) {
            float* __restrict__ d = base + (size_t)r * ENC_LEN;
            st32B(d + offA, qa);
            st32B(d + offB, qb);
        }
    }
}

extern "C" void kernel_launch(void* const* d_in, const int* in_sizes, int n_in,
                              void* d_out, int out_size) {
    // setup_inputs order: length (scalar), n (scalar), position (float[1]).
    const float* position = (const float*)d_in[n_in - 1];

    const int n = out_size / ENC_LEN;     // 4096

    int grid = (n + ROWS_PER_CTA - 1) / ROWS_PER_CTA;   // 586
    sinusoidal_fused_kernel<<<grid, BLOCK>>>(position, (float*)d_out, n);
}

// round 10
// speedup vs baseline: 1.0739x; 1.0739x over previous
#include <cuda_runtime.h>
#include <cuda_bf16.h>

// Problem constants (fixed by setup_inputs): length=8192, n=4096.
#define ENC_LEN   8192
#define BLOCK     512

// inv_freq(base) = 1000^(-base/8192) = exp2(-(base/8192) * log2(1000))
// Compensated fp32 product keeps the exp2 argument accurate to ~1 ulp.
__device__ __forceinline__ float inv_freq(int base) {
    const double Ld = 9.965784284662087;          // log2(1000)
    const float  Lh = (float)Ld;
    const float  Ll = (float)(Ld - (double)Lh);   // low-order correction
    float e   = (float)base * (1.0f / 8192.0f);   // exact (base < 2^13)
    float p   = e * Lh;
    float err = fmaf(e, Lh, -p);                  // exact residual of e*Lh
    float t   = p + fmaf(e, Ll, err);             // ≈ e * log2(1000)
    return exp2f(-t);
}

__device__ __forceinline__ unsigned long long pack2(float x, float y) {
    unsigned long long r;
    asm("mov.b64 %0, {%1, %2};" : "=l"(r) : "f"(x), "f"(y));
    return r;
}

// Plain 32-byte store, default L2 policy. Measured across 9 rounds:
//  - cache hints (.cs, evict_last) never beat default;
//  - strided row assignment beats contiguous blocks (uniform L2-slice/HBM-
//    channel spread at every instant);
//  - grid 592 + 2-row stride + 256-bit stores is the optimum (25.09us).
__device__ __forceinline__ void st32B(void* p, const unsigned long long* q) {
    asm volatile("st.global.v4.b64 [%0], {%1, %2, %3, %4};"
                 :: "l"(p), "l"(q[0]), "l"(q[1]), "l"(q[2]), "l"(q[3])
                 : "memory");
}

// ---------------------------------------------------------------------------
// Fused kernel. Each thread owns two contiguous 32B chunks of the row:
//   chunk A: elements [8t, 8t+8)
//   chunk B: elements [8t+4096, 8t+4104)
// computed once into registers (8 sincosf + 8 exp2f), then broadcast to all
// n rows with 256-bit stores, 2 rows per iteration (4 independent stores in
// flight per warp). Runtime: HBM/LTS write-bound at the chip floor.
// ---------------------------------------------------------------------------
__global__ void __launch_bounds__(BLOCK)
sinusoidal_fused_kernel(const float* __restrict__ position,
                        float* __restrict__ out, int n) {
    const int tid = threadIdx.x;
    const float pos = position[0];

    unsigned long long qa[4], qb[4];
#pragma unroll
    for (int k = 0; k < 4; ++k) {
        int baseA = 8 * tid + 2 * k;
        float aA = pos * inv_freq(baseA);
        float sA, cA;
        sincosf(aA, &sA, &cA);
        qa[k] = pack2(sA, cA);

        int baseB = baseA + 4096;
        float aB = pos * inv_freq(baseB);
        float sB, cB;
        sincosf(aB, &sB, &cB);
        qb[k] = pack2(sB, cB);
    }

    const int offA = 8 * tid;
    const int offB = 8 * tid + 4096;

    // 2-row unrolled, grid-strided broadcast loop.
    int row = blockIdx.x * 2;
    const int stride = gridDim.x * 2;
    for (; row + 1 < n; row += stride) {
        float* __restrict__ d0 = out + (size_t)row * ENC_LEN;
        float* __restrict__ d1 = d0 + ENC_LEN;
        st32B(d0 + offA, qa);
        st32B(d0 + offB, qb);
        st32B(d1 + offA, qa);
        st32B(d1 + offB, qb);
    }
    if (row < n) {
        float* __restrict__ d0 = out + (size_t)row * ENC_LEN;
        st32B(d0 + offA, qa);
        st32B(d0 + offB, qb);
    }
}

extern "C" void kernel_launch(void* const* d_in, const int* in_sizes, int n_in,
                              void* d_out, int out_size) {
    // setup_inputs order: length (scalar), n (scalar), position (float[1]).
    const float* position = (const float*)d_in[n_in - 1];

    const int n = out_size / ENC_LEN;     // 4096

    // 4 CTAs/SM (148 SMs) -> 592 CTAs, the measured-best grid.
    int grid = 592;
    if (grid * 2 > n) grid = (n + 1) / 2;
    sinusoidal_fused_kernel<<<grid, BLOCK>>>(position, (float*)d_out, n);
}

// round 11
// speedup vs baseline: 1.0753x; 1.0013x over previous
#include <cuda_runtime.h>
#include <cuda_bf16.h>

// Problem constants (fixed by setup_inputs): length=8192, n=4096.
#define ENC_LEN   8192
#define BLOCK     512

// inv_freq(base) = 1000^(-base/8192) = exp2(-(base/8192) * log2(1000))
// Compensated fp32 product keeps the exp2 argument accurate to ~1 ulp.
__device__ __forceinline__ float inv_freq(int base) {
    const double Ld = 9.965784284662087;          // log2(1000)
    const float  Lh = (float)Ld;
    const float  Ll = (float)(Ld - (double)Lh);   // low-order correction
    float e   = (float)base * (1.0f / 8192.0f);   // exact (base < 2^13)
    float p   = e * Lh;
    float err = fmaf(e, Lh, -p);                  // exact residual of e*Lh
    float t   = p + fmaf(e, Ll, err);             // ≈ e * log2(1000)
    return exp2f(-t);
}

__device__ __forceinline__ unsigned long long pack2(float x, float y) {
    unsigned long long r;
    asm("mov.b64 %0, {%1, %2};" : "=l"(r) : "f"(x), "f"(y));
    return r;
}

// Plain 32-byte store, default L2 policy. Measured across 10 rounds:
//  - cache hints (.cs, evict_last) never beat default;
//  - strided row assignment beats contiguous blocks (uniform L2-slice/HBM-
//    channel spread at every instant);
//  - grid 592 + 2-row stride + 256-bit stores is the confirmed optimum
//    (25.09us / 25.12us on two independent benches = HBM-write floor:
//    134MB @ 5.35TB/s sustained write).
__device__ __forceinline__ void st32B(void* p, const unsigned long long* q) {
    asm volatile("st.global.v4.b64 [%0], {%1, %2, %3, %4};"
                 :: "l"(p), "l"(q[0]), "l"(q[1]), "l"(q[2]), "l"(q[3])
                 : "memory");
}

// ---------------------------------------------------------------------------
// Fused kernel. Each thread owns two contiguous 32B chunks of the row:
//   chunk A: elements [8t, 8t+8)
//   chunk B: elements [8t+4096, 8t+4104)
// computed once into registers (8 sincosf + 8 exp2f), then broadcast to all
// n rows with 256-bit stores, 2 rows per iteration (4 independent stores in
// flight per warp). Runtime: HBM write-bound at the chip floor.
// ---------------------------------------------------------------------------
__global__ void __launch_bounds__(BLOCK)
sinusoidal_fused_kernel(const float* __restrict__ position,
                        float* __restrict__ out, int n) {
    const int tid = threadIdx.x;
    const float pos = position[0];

    unsigned long long qa[4], qb[4];
#pragma unroll
    for (int k = 0; k < 4; ++k) {
        int baseA = 8 * tid + 2 * k;
        float aA = pos * inv_freq(baseA);
        float sA, cA;
        sincosf(aA, &sA, &cA);
        qa[k] = pack2(sA, cA);

        int baseB = baseA + 4096;
        float aB = pos * inv_freq(baseB);
        float sB, cB;
        sincosf(aB, &sB, &cB);
        qb[k] = pack2(sB, cB);
    }

    const int offA = 8 * tid;
    const int offB = 8 * tid + 4096;

    // 2-row unrolled, grid-strided broadcast loop.
    int row = blockIdx.x * 2;
    const int stride = gridDim.x * 2;
    for (; row + 1 < n; row += stride) {
        float* __restrict__ d0 = out + (size_t)row * ENC_LEN;
        float* __restrict__ d1 = d0 + ENC_LEN;
        st32B(d0 + offA, qa);
        st32B(d0 + offB, qb);
        st32B(d1 + offA, qa);
        st32B(d1 + offB, qb);
    }
    if (row < n) {
        float* __restrict__ d0 = out + (size_t)row * ENC_LEN;
        st32B(d0 + offA, qa);
        st32B(d0 + offB, qb);
    }
}

extern "C" void kernel_launch(void* const* d_in, const int* in_sizes, int n_in,
                              void* d_out, int out_size) {
    // setup_inputs order: length (scalar), n (scalar), position (float[1]).
    const float* position = (const float*)d_in[n_in - 1];

    const int n = out_size / ENC_LEN;     // 4096

    // 4 CTAs/SM (148 SMs) -> 592 CTAs, the measured-best grid.
    int grid = 592;
    if (grid * 2 > n) grid = (n + 1) / 2;
    sinusoidal_fused_kernel<<<grid, BLOCK>>>(position, (float*)d_out, n);
}